// round 3
// baseline (speedup 1.0000x reference)
#include <cuda_runtime.h>
#include <cuda_fp16.h>

// ---------------------------------------------------------------------------
// LapImage R3: spatial counting-sort for warp-coherent gathers.
//
// R2 established the kernel is l1tex-wavefront bound (~1 wf per distinct line
// per gather per warp). Random coords -> 32 distinct lines per gather. Fix:
// sort points into 64x64x32 spatial bins so each warp's 32 points are
// neighbors; gathers then touch few distinct lines (esp. for the coarse
// volumes). Sample in sorted order, inverse-permute the results back.
//
// Volumes stay in the R2 fp16 E/O x-pair format (4 x 16B gathers / volume).
// ---------------------------------------------------------------------------

static constexpr int D0 = 32, H0 = 32,  W0 = 32;
static constexpr int D1 = 32, H1 = 64,  W1 = 64;
static constexpr int D2 = 32, H2 = 128, W2 = 128;
static constexpr int D3 = 32, H3 = 256, W3 = 256;
static constexpr int NV0 = D0 * H0 * W0;
static constexpr int NV1 = D1 * H1 * W1;
static constexpr int NV2 = D2 * H2 * W2;
static constexpr int NV3 = D3 * H3 * W3;
static constexpr int NV_TOTAL = NV0 + NV1 + NV2 + NV3;

static constexpr int BVOL = 96 * 96 * 96;   // 884736
static constexpr int NPTS = 4 * BVOL;       // 3538944 = 13824 * 256

// Spatial bins: 64 x 64 x 32
static constexpr int BX = 64, BY = 64, BZ = 32;
static constexpr int NBINS = BX * BY * BZ;  // 131072 = 512 * 256

// ---- volume storage (R2 E/O format) ----
__device__ __align__(16) uint2 g_e0[NV0];  __device__ __align__(16) uint2 g_o0[NV0];
__device__ __align__(16) uint2 g_e1[NV1];  __device__ __align__(16) uint2 g_o1[NV1];
__device__ __align__(16) uint2 g_e2[NV2];  __device__ __align__(16) uint2 g_o2[NV2];
__device__ __align__(16) uint2 g_e3[NV3];  __device__ __align__(16) uint2 g_o3[NV3];

// ---- sort scratch ----
__device__ int    g_keys[NPTS];
__device__ int    g_inv[NPTS];       // orig index -> sorted position
__device__ float4 g_sorted[NPTS];    // sorted coords
__device__ float4 g_res[NPTS];       // results in sorted order
__device__ int    g_hist[NBINS];
__device__ int    g_boff[NBINS];
__device__ int    g_bsums[512];

// ---------------------------------------------------------------------------
// Pack: [3,D,H,W] fp32 -> half4 voxels in E[i] and O[i-1].
// ---------------------------------------------------------------------------
__device__ __forceinline__ void pack_one(const float* __restrict__ s, int i, int nv,
                                         uint2* __restrict__ E, uint2* __restrict__ O)
{
    __half h0 = __float2half_rn(s[i]);
    __half h1 = __float2half_rn(s[i + nv]);
    __half h2 = __float2half_rn(s[i + 2 * nv]);
    __half2 lo = __halves2half2(h0, h1);
    __half2 hi = __halves2half2(h2, __ushort_as_half((unsigned short)0));
    uint2 u;
    u.x = *reinterpret_cast<unsigned int*>(&lo);
    u.y = *reinterpret_cast<unsigned int*>(&hi);
    E[i] = u;
    if (i > 0) O[i - 1] = u;
}

__global__ void __launch_bounds__(256) pack_kernel(
    const float* __restrict__ s0, const float* __restrict__ s1,
    const float* __restrict__ s2, const float* __restrict__ s3)
{
    int i = blockIdx.x * 256 + threadIdx.x;
    if (i < NV0) { pack_one(s0, i, NV0, g_e0, g_o0); return; }
    i -= NV0;
    if (i < NV1) { pack_one(s1, i, NV1, g_e1, g_o1); return; }
    i -= NV1;
    if (i < NV2) { pack_one(s2, i, NV2, g_e2, g_o2); return; }
    i -= NV2;
    if (i < NV3) { pack_one(s3, i, NV3, g_e3, g_o3); }
}

// ---------------------------------------------------------------------------
// Sort pipeline
// ---------------------------------------------------------------------------
__global__ void __launch_bounds__(256) zero_hist_kernel()
{
    g_hist[blockIdx.x * 256 + threadIdx.x] = 0;
}

__device__ __forceinline__ int coord_key(float gx, float gy, float gz)
{
    int bx = (int)(fminf(fmaxf((gx + 1.0f) * 0.5f, 0.0f), 0.999999f) * (float)BX);
    int by = (int)(fminf(fmaxf((gy + 1.0f) * 0.5f, 0.0f), 0.999999f) * (float)BY);
    int bz = (int)(fminf(fmaxf((gz + 1.0f) * 0.5f, 0.0f), 0.999999f) * (float)BZ);
    bx = min(bx, BX - 1); by = min(by, BY - 1); bz = min(bz, BZ - 1);
    return (bz * BY + by) * BX + bx;
}

__global__ void __launch_bounds__(256) hist_kernel(const float* __restrict__ coords)
{
    __shared__ float sc[768];
    int t = threadIdx.x;
    int base = blockIdx.x * 256;
    const float4* c4 = reinterpret_cast<const float4*>(coords + (size_t)base * 3);
    if (t < 192) {
        float4 v = __ldg(c4 + t);
        sc[4 * t + 0] = v.x; sc[4 * t + 1] = v.y;
        sc[4 * t + 2] = v.z; sc[4 * t + 3] = v.w;
    }
    __syncthreads();
    int key = coord_key(sc[3 * t], sc[3 * t + 1], sc[3 * t + 2]);
    g_keys[base + t] = key;
    atomicAdd(&g_hist[key], 1);
}

// scan1: per-block (256-wide) exclusive scan of hist -> boff, block totals.
__global__ void __launch_bounds__(256) scan1_kernel()
{
    __shared__ int wsum[8];
    int b = blockIdx.x, t = threadIdx.x;
    int lane = t & 31, w = t >> 5;
    int v = g_hist[b * 256 + t];
    int x = v;
    #pragma unroll
    for (int o = 1; o < 32; o <<= 1) {
        int y = __shfl_up_sync(0xFFFFFFFFu, x, o);
        if (lane >= o) x += y;
    }
    if (lane == 31) wsum[w] = x;
    __syncthreads();
    if (t < 8) {
        int s = wsum[t];
        int xs = s;
        #pragma unroll
        for (int o = 1; o < 8; o <<= 1) {
            int y = __shfl_up_sync(0xFFu, xs, o);
            if (t >= o) xs += y;
        }
        wsum[t] = xs - s;   // exclusive warp offset
    }
    __syncthreads();
    int excl = x - v + wsum[w];
    g_boff[b * 256 + t] = excl;
    if (t == 255) g_bsums[b] = excl + v;
}

// scan2: single block, exclusive scan of the 512 block sums.
__global__ void __launch_bounds__(512) scan2_kernel()
{
    __shared__ int wsum[16];
    int t = threadIdx.x, lane = t & 31, w = t >> 5;
    int v = g_bsums[t];
    int x = v;
    #pragma unroll
    for (int o = 1; o < 32; o <<= 1) {
        int y = __shfl_up_sync(0xFFFFFFFFu, x, o);
        if (lane >= o) x += y;
    }
    if (lane == 31) wsum[w] = x;
    __syncthreads();
    if (t < 16) {
        int s = wsum[t];
        int xs = s;
        #pragma unroll
        for (int o = 1; o < 16; o <<= 1) {
            int y = __shfl_up_sync(0xFFFFu, xs, o);
            if (t >= o) xs += y;
        }
        wsum[t] = xs - s;
    }
    __syncthreads();
    g_bsums[t] = x - v + wsum[w];
}

// scan3: add scanned block sums back.
__global__ void __launch_bounds__(256) scan3_kernel()
{
    int i = blockIdx.x * 256 + threadIdx.x;
    g_boff[i] += g_bsums[blockIdx.x];
}

// scatter: place each point at its sorted position; record inverse perm.
__global__ void __launch_bounds__(256) scatter_kernel(const float* __restrict__ coords)
{
    __shared__ float sc[768];
    int t = threadIdx.x;
    int base = blockIdx.x * 256;
    const float4* c4 = reinterpret_cast<const float4*>(coords + (size_t)base * 3);
    if (t < 192) {
        float4 v = __ldg(c4 + t);
        sc[4 * t + 0] = v.x; sc[4 * t + 1] = v.y;
        sc[4 * t + 2] = v.z; sc[4 * t + 3] = v.w;
    }
    __syncthreads();
    int n = base + t;
    int key = g_keys[n];
    int pos = atomicAdd(&g_boff[key], 1);
    g_sorted[pos] = make_float4(sc[3 * t], sc[3 * t + 1], sc[3 * t + 2], 0.0f);
    g_inv[n] = pos;
}

// ---------------------------------------------------------------------------
// Trilinear sample (R2 math, E/O pair loads)
// ---------------------------------------------------------------------------
__device__ __forceinline__ void acc_pair(uint4 q, float w, float fx,
                                         float& ax, float& ay, float& az)
{
    const __half2* h = reinterpret_cast<const __half2*>(&q);
    float2 a01 = __half22float2(h[0]);
    float  a2  = __low2float(h[1]);
    float2 b01 = __half22float2(h[2]);
    float  b2  = __low2float(h[3]);
    float cx = fmaf(fx, b01.x - a01.x, a01.x);
    float cy = fmaf(fx, b01.y - a01.y, a01.y);
    float cz = fmaf(fx, b2    - a2,    a2);
    ax = fmaf(w, cx, ax);
    ay = fmaf(w, cy, ay);
    az = fmaf(w, cz, az);
}

template <int D, int H, int W>
__device__ __forceinline__ void sample_vol(
    const uint2* __restrict__ E, const uint2* __restrict__ O,
    float gx, float gy, float gz,
    float& ax, float& ay, float& az)
{
    const float hx = 0.5f * (float)(W - 1);
    const float hy = 0.5f * (float)(H - 1);
    const float hz = 0.5f * (float)(D - 1);
    float ix = fminf(fmaxf(fmaf(gx, hx, hx), 0.0f), (float)(W - 1));
    float iy = fminf(fmaxf(fmaf(gy, hy, hy), 0.0f), (float)(H - 1));
    float iz = fminf(fmaxf(fmaf(gz, hz, hz), 0.0f), (float)(D - 1));

    int x0 = min((int)ix, W - 2);
    int y0 = min((int)iy, H - 2);
    int z0 = min((int)iz, D - 2);
    float fx = ix - (float)x0;
    float fy = iy - (float)y0;
    float fz = iz - (float)z0;

    int r00 = (z0 * H + y0) * W;
    int r01 = r00 + W;
    int r10 = r00 + H * W;
    int r11 = r10 + W;

    int odd = x0 & 1;
    const uint2* arr = odd ? O : E;
    int xo = x0 - odd;

    uint4 q00 = __ldg(reinterpret_cast<const uint4*>(arr + (r00 + xo)));
    uint4 q01 = __ldg(reinterpret_cast<const uint4*>(arr + (r01 + xo)));
    uint4 q10 = __ldg(reinterpret_cast<const uint4*>(arr + (r10 + xo)));
    uint4 q11 = __ldg(reinterpret_cast<const uint4*>(arr + (r11 + xo)));

    float ez = 1.0f - fz, ey = 1.0f - fy;
    acc_pair(q00, ez * ey, fx, ax, ay, az);
    acc_pair(q01, ez * fy, fx, ax, ay, az);
    acc_pair(q10, fz * ey, fx, ax, ay, az);
    acc_pair(q11, fz * fy, fx, ax, ay, az);
}

// ---------------------------------------------------------------------------
// Sample in sorted order (coalesced float4 in, coalesced float4 out).
// ---------------------------------------------------------------------------
__global__ void __launch_bounds__(256) sample_sorted_kernel(float* __restrict__ dummy)
{
    int i = blockIdx.x * 256 + threadIdx.x;
    float4 c = g_sorted[i];

    float ax = 0.0f, ay = 0.0f, az = 0.0f;
    sample_vol<D0, H0, W0>(g_e0, g_o0, c.x, c.y, c.z, ax, ay, az);
    sample_vol<D1, H1, W1>(g_e1, g_o1, c.x, c.y, c.z, ax, ay, az);
    sample_vol<D2, H2, W2>(g_e2, g_o2, c.x, c.y, c.z, ax, ay, az);
    sample_vol<D3, H3, W3>(g_e3, g_o3, c.x, c.y, c.z, ax, ay, az);

    g_res[i] = make_float4(ax, ay, az, 0.0f);
    (void)dummy;
}

// ---------------------------------------------------------------------------
// Unpermute: out[b][c][v] from g_res via inverse perm (1 random 16B gather/pt).
// ---------------------------------------------------------------------------
__global__ void __launch_bounds__(256) unpermute_kernel(float* __restrict__ out)
{
    int m = blockIdx.x * 256 + threadIdx.x;
    int pos = g_inv[m];
    float4 r = __ldg(&g_res[pos]);
    int b = m / BVOL;
    int v = m - b * BVOL;
    float* o = out + (size_t)(b * 3) * BVOL + v;
    o[0]        = r.x;
    o[BVOL]     = r.y;
    o[2 * BVOL] = r.z;
}

// ---------------------------------------------------------------------------
// Launch
// ---------------------------------------------------------------------------
extern "C" void kernel_launch(void* const* d_in, const int* in_sizes, int n_in,
                              void* d_out, int out_size)
{
    const float* coords = (const float*)d_in[0];
    const float* img0   = (const float*)d_in[1];
    const float* img1   = (const float*)d_in[2];
    const float* img2   = (const float*)d_in[3];
    const float* img3   = (const float*)d_in[4];
    float*       out    = (float*)d_out;

    pack_kernel<<<NV_TOTAL / 256, 256>>>(img0, img1, img2, img3);
    zero_hist_kernel<<<NBINS / 256, 256>>>();
    hist_kernel<<<NPTS / 256, 256>>>(coords);
    scan1_kernel<<<NBINS / 256, 256>>>();
    scan2_kernel<<<1, 512>>>();
    scan3_kernel<<<NBINS / 256, 256>>>();
    scatter_kernel<<<NPTS / 256, 256>>>(coords);
    sample_sorted_kernel<<<NPTS / 256, 256>>>(out);
    unpermute_kernel<<<NPTS / 256, 256>>>(out);
}

// round 5
// speedup vs baseline: 1.1456x; 1.1456x over previous
#include <cuda_runtime.h>
#include <cuda_fp16.h>

// ---------------------------------------------------------------------------
// LapImage R4: fixed-capacity bucket scatter (no histogram/scan) + warp-
// coherent sampling.
//
// R2: unsorted sample is l1tex-bound at 16 wf/pt (218us).
// R3: full counting sort halved sample but pipeline overhead (hist+scan+
//     scatter, ~7M atomics, 6 extra passes) cost more than it saved.
// R4: single-pass bucket scatter: bins 16x256x32 (mean 27 pts), CAP=32 ->
//     one warp per bucket. Overflow (~2%) spills to a list handled by a
//     small unsorted pass. Bins are LONG IN X (along cache lines) so each
//     gather instruction touches ~2-3 lines instead of 32.
// Deterministic: atomic order only picks slots/paths; every path computes
// the identical fp16-sourced value for a given point.
// ---------------------------------------------------------------------------

static constexpr int D0 = 32, H0 = 32,  W0 = 32;
static constexpr int D1 = 32, H1 = 64,  W1 = 64;
static constexpr int D2 = 32, H2 = 128, W2 = 128;
static constexpr int D3 = 32, H3 = 256, W3 = 256;
static constexpr int NV0 = D0 * H0 * W0;
static constexpr int NV1 = D1 * H1 * W1;
static constexpr int NV2 = D2 * H2 * W2;
static constexpr int NV3 = D3 * H3 * W3;
static constexpr int NV_TOTAL = NV0 + NV1 + NV2 + NV3;

static constexpr int BVOL = 96 * 96 * 96;   // 884736
static constexpr int NPTS = 4 * BVOL;       // 3538944 = 13824 * 256

// Spatial bins: long in x. 16 x 256 x 32 = 131072 bins, mean 27 pts/bin.
static constexpr int SBX = 16, SBY = 256, SBZ = 32;
static constexpr int NB  = SBX * SBY * SBZ;    // 131072
static constexpr int CAP = 32;                 // one warp per bucket
static constexpr int NSLOTS = NB * CAP;        // 4194304

// ---- volume storage (fp16 half4 voxels, E/O x-pair duplicates) ----
__device__ __align__(16) uint2 g_e0[NV0];  __device__ __align__(16) uint2 g_o0[NV0];
__device__ __align__(16) uint2 g_e1[NV1];  __device__ __align__(16) uint2 g_o1[NV1];
__device__ __align__(16) uint2 g_e2[NV2];  __device__ __align__(16) uint2 g_o2[NV2];
__device__ __align__(16) uint2 g_e3[NV3];  __device__ __align__(16) uint2 g_o3[NV3];

// ---- bucket scratch ----
__device__ int    g_cnt[NB];
__device__ int    g_novf;
__device__ int    g_inv[NPTS];                 // orig idx -> result position
__device__ float4 g_sorted[NSLOTS];            // bucketed coords
__device__ float4 g_ovf[NPTS];                 // overflow coords (worst case)
__device__ float4 g_res[NSLOTS + NPTS];        // results: buckets then overflow

// ---------------------------------------------------------------------------
// Pack: [3,D,H,W] fp32 -> half4 voxels in E[i] and O[i-1].
// ---------------------------------------------------------------------------
__device__ __forceinline__ void pack_one(const float* __restrict__ s, int i, int nv,
                                         uint2* __restrict__ E, uint2* __restrict__ O)
{
    __half h0 = __float2half_rn(s[i]);
    __half h1 = __float2half_rn(s[i + nv]);
    __half h2 = __float2half_rn(s[i + 2 * nv]);
    __half2 lo = __halves2half2(h0, h1);
    __half2 hi = __halves2half2(h2, __ushort_as_half((unsigned short)0));
    uint2 u;
    u.x = *reinterpret_cast<unsigned int*>(&lo);
    u.y = *reinterpret_cast<unsigned int*>(&hi);
    E[i] = u;
    if (i > 0) O[i - 1] = u;
}

__global__ void __launch_bounds__(256) pack_kernel(
    const float* __restrict__ s0, const float* __restrict__ s1,
    const float* __restrict__ s2, const float* __restrict__ s3)
{
    int i = blockIdx.x * 256 + threadIdx.x;
    if (i < NV0) { pack_one(s0, i, NV0, g_e0, g_o0); return; }
    i -= NV0;
    if (i < NV1) { pack_one(s1, i, NV1, g_e1, g_o1); return; }
    i -= NV1;
    if (i < NV2) { pack_one(s2, i, NV2, g_e2, g_o2); return; }
    i -= NV2;
    if (i < NV3) { pack_one(s3, i, NV3, g_e3, g_o3); }
}

// ---------------------------------------------------------------------------
// Zero bucket counters.
// ---------------------------------------------------------------------------
__global__ void __launch_bounds__(256) zero_kernel()
{
    int i = blockIdx.x * 256 + threadIdx.x;
    g_cnt[i] = 0;
    if (i == 0) g_novf = 0;
}

// ---------------------------------------------------------------------------
// Scatter: single pass. pos = key*CAP + atomicAdd; overflow -> list.
// ---------------------------------------------------------------------------
__device__ __forceinline__ int coord_key(float gx, float gy, float gz)
{
    int bx = (int)(fminf(fmaxf((gx + 1.0f) * 0.5f, 0.0f), 0.999999f) * (float)SBX);
    int by = (int)(fminf(fmaxf((gy + 1.0f) * 0.5f, 0.0f), 0.999999f) * (float)SBY);
    int bz = (int)(fminf(fmaxf((gz + 1.0f) * 0.5f, 0.0f), 0.999999f) * (float)SBZ);
    bx = min(bx, SBX - 1); by = min(by, SBY - 1); bz = min(bz, SBZ - 1);
    return (bz * SBY + by) * SBX + bx;
}

__global__ void __launch_bounds__(256) scatter_kernel(const float* __restrict__ coords)
{
    __shared__ float sc[768];
    int t = threadIdx.x;
    int base = blockIdx.x * 256;
    const float4* c4 = reinterpret_cast<const float4*>(coords + (size_t)base * 3);
    if (t < 192) {
        float4 v = __ldg(c4 + t);
        sc[4 * t + 0] = v.x; sc[4 * t + 1] = v.y;
        sc[4 * t + 2] = v.z; sc[4 * t + 3] = v.w;
    }
    __syncthreads();

    float gx = sc[3 * t], gy = sc[3 * t + 1], gz = sc[3 * t + 2];
    int n = base + t;
    int key = coord_key(gx, gy, gz);
    int c = atomicAdd(&g_cnt[key], 1);
    if (c < CAP) {
        int pos = key * CAP + c;
        g_sorted[pos] = make_float4(gx, gy, gz, 0.0f);
        g_inv[n] = pos;
    } else {
        int j = atomicAdd(&g_novf, 1);
        g_ovf[j] = make_float4(gx, gy, gz, 0.0f);
        g_inv[n] = NSLOTS + j;
    }
}

// ---------------------------------------------------------------------------
// Trilinear sample (fp16 E/O pair loads, fp32 math)
// ---------------------------------------------------------------------------
__device__ __forceinline__ void acc_pair(uint4 q, float w, float fx,
                                         float& ax, float& ay, float& az)
{
    const __half2* h = reinterpret_cast<const __half2*>(&q);
    float2 a01 = __half22float2(h[0]);
    float  a2  = __low2float(h[1]);
    float2 b01 = __half22float2(h[2]);
    float  b2  = __low2float(h[3]);
    float cx = fmaf(fx, b01.x - a01.x, a01.x);
    float cy = fmaf(fx, b01.y - a01.y, a01.y);
    float cz = fmaf(fx, b2    - a2,    a2);
    ax = fmaf(w, cx, ax);
    ay = fmaf(w, cy, ay);
    az = fmaf(w, cz, az);
}

template <int D, int H, int W>
__device__ __forceinline__ void sample_vol(
    const uint2* __restrict__ E, const uint2* __restrict__ O,
    float gx, float gy, float gz,
    float& ax, float& ay, float& az)
{
    const float hx = 0.5f * (float)(W - 1);
    const float hy = 0.5f * (float)(H - 1);
    const float hz = 0.5f * (float)(D - 1);
    float ix = fminf(fmaxf(fmaf(gx, hx, hx), 0.0f), (float)(W - 1));
    float iy = fminf(fmaxf(fmaf(gy, hy, hy), 0.0f), (float)(H - 1));
    float iz = fminf(fmaxf(fmaf(gz, hz, hz), 0.0f), (float)(D - 1));

    int x0 = min((int)ix, W - 2);
    int y0 = min((int)iy, H - 2);
    int z0 = min((int)iz, D - 2);
    float fx = ix - (float)x0;
    float fy = iy - (float)y0;
    float fz = iz - (float)z0;

    int r00 = (z0 * H + y0) * W;
    int r01 = r00 + W;
    int r10 = r00 + H * W;
    int r11 = r10 + W;

    int odd = x0 & 1;
    const uint2* arr = odd ? O : E;
    int xo = x0 - odd;

    uint4 q00 = __ldg(reinterpret_cast<const uint4*>(arr + (r00 + xo)));
    uint4 q01 = __ldg(reinterpret_cast<const uint4*>(arr + (r01 + xo)));
    uint4 q10 = __ldg(reinterpret_cast<const uint4*>(arr + (r10 + xo)));
    uint4 q11 = __ldg(reinterpret_cast<const uint4*>(arr + (r11 + xo)));

    float ez = 1.0f - fz, ey = 1.0f - fy;
    acc_pair(q00, ez * ey, fx, ax, ay, az);
    acc_pair(q01, ez * fy, fx, ax, ay, az);
    acc_pair(q10, fz * ey, fx, ax, ay, az);
    acc_pair(q11, fz * fy, fx, ax, ay, az);
}

__device__ __forceinline__ float4 sample_all(float gx, float gy, float gz)
{
    float ax = 0.0f, ay = 0.0f, az = 0.0f;
    sample_vol<D0, H0, W0>(g_e0, g_o0, gx, gy, gz, ax, ay, az);
    sample_vol<D1, H1, W1>(g_e1, g_o1, gx, gy, gz, ax, ay, az);
    sample_vol<D2, H2, W2>(g_e2, g_o2, gx, gy, gz, ax, ay, az);
    sample_vol<D3, H3, W3>(g_e3, g_o3, gx, gy, gz, ax, ay, az);
    return make_float4(ax, ay, az, 0.0f);
}

// ---------------------------------------------------------------------------
// Bucket sample: one warp per bucket; lanes >= count inert.
// ---------------------------------------------------------------------------
__global__ void __launch_bounds__(256) sample_bucket_kernel()
{
    int warp = blockIdx.x * 8 + (threadIdx.x >> 5);
    int lane = threadIdx.x & 31;
    int cnt = min(g_cnt[warp], CAP);
    if (lane < cnt) {
        int pos = warp * CAP + lane;
        float4 c = g_sorted[pos];
        g_res[pos] = sample_all(c.x, c.y, c.z);
    }
}

// ---------------------------------------------------------------------------
// Overflow sample: grid-stride over the (tiny) overflow list, unsorted.
// ---------------------------------------------------------------------------
__global__ void __launch_bounds__(256) sample_ovf_kernel()
{
    int total = g_novf;
    for (int j = blockIdx.x * 256 + threadIdx.x; j < total; j += gridDim.x * 256) {
        float4 c = g_ovf[j];
        g_res[NSLOTS + j] = sample_all(c.x, c.y, c.z);
    }
}

// ---------------------------------------------------------------------------
// Unpermute: out[b][c][v] <- g_res[g_inv[n]]  (1 random 16B gather/pt).
// ---------------------------------------------------------------------------
__global__ void __launch_bounds__(256) unpermute_kernel(float* __restrict__ out)
{
    int m = blockIdx.x * 256 + threadIdx.x;
    int pos = g_inv[m];
    float4 r = __ldg(&g_res[pos]);
    int b = m / BVOL;
    int v = m - b * BVOL;
    float* o = out + (size_t)(b * 3) * BVOL + v;
    o[0]        = r.x;
    o[BVOL]     = r.y;
    o[2 * BVOL] = r.z;
}

// ---------------------------------------------------------------------------
// Launch
// ---------------------------------------------------------------------------
extern "C" void kernel_launch(void* const* d_in, const int* in_sizes, int n_in,
                              void* d_out, int out_size)
{
    const float* coords = (const float*)d_in[0];
    const float* img0   = (const float*)d_in[1];
    const float* img1   = (const float*)d_in[2];
    const float* img2   = (const float*)d_in[3];
    const float* img3   = (const float*)d_in[4];
    float*       out    = (float*)d_out;

    pack_kernel<<<NV_TOTAL / 256, 256>>>(img0, img1, img2, img3);
    zero_kernel<<<NB / 256, 256>>>();
    scatter_kernel<<<NPTS / 256, 256>>>(coords);
    sample_bucket_kernel<<<NB / 8, 256>>>();       // 1 warp per bucket
    sample_ovf_kernel<<<512, 256>>>();
    unpermute_kernel<<<NPTS / 256, 256>>>(out);
}

// round 6
// speedup vs baseline: 1.1569x; 1.0098x over previous
#include <cuda_runtime.h>
#include <cuda_fp16.h>

// ---------------------------------------------------------------------------
// LapImage R5: bucket scatter + warp-coherent sampling + half2 lerp.
//
// R4 made sample_bucket dual-limited (L1 91%, issue 55%, ~200 instr/warp of
// which ~96 were F2F cvts). R5 does the x-lerp in half2 (HSUB2/HFMA2) on the
// raw fp16 pair data and converts only the 3 interpolated channel values to
// fp32 -> ~10 instr/pair instead of ~15. Weighted accumulation stays fp32.
// zero_kernel folded into pack_kernel; unpermute does 2 pts/thread for MLP.
// ---------------------------------------------------------------------------

static constexpr int D0 = 32, H0 = 32,  W0 = 32;
static constexpr int D1 = 32, H1 = 64,  W1 = 64;
static constexpr int D2 = 32, H2 = 128, W2 = 128;
static constexpr int D3 = 32, H3 = 256, W3 = 256;
static constexpr int NV0 = D0 * H0 * W0;
static constexpr int NV1 = D1 * H1 * W1;
static constexpr int NV2 = D2 * H2 * W2;
static constexpr int NV3 = D3 * H3 * W3;
static constexpr int NV_TOTAL = NV0 + NV1 + NV2 + NV3;

static constexpr int BVOL = 96 * 96 * 96;   // 884736
static constexpr int NPTS = 4 * BVOL;       // 3538944 = 13824 * 256

// Spatial bins: long in x. 16 x 256 x 32 = 131072 bins, mean 27 pts/bin.
static constexpr int SBX = 16, SBY = 256, SBZ = 32;
static constexpr int NB  = SBX * SBY * SBZ;    // 131072
static constexpr int CAP = 32;                 // one warp per bucket
static constexpr int NSLOTS = NB * CAP;        // 4194304

// ---- volume storage (fp16 half4 voxels, E/O x-pair duplicates) ----
__device__ __align__(16) uint2 g_e0[NV0];  __device__ __align__(16) uint2 g_o0[NV0];
__device__ __align__(16) uint2 g_e1[NV1];  __device__ __align__(16) uint2 g_o1[NV1];
__device__ __align__(16) uint2 g_e2[NV2];  __device__ __align__(16) uint2 g_o2[NV2];
__device__ __align__(16) uint2 g_e3[NV3];  __device__ __align__(16) uint2 g_o3[NV3];

// ---- bucket scratch ----
__device__ int    g_cnt[NB];
__device__ int    g_novf;
__device__ int    g_inv[NPTS];                 // orig idx -> result position
__device__ float4 g_sorted[NSLOTS];            // bucketed coords
__device__ float4 g_ovf[NPTS];                 // overflow coords (worst case)
__device__ float4 g_res[NSLOTS + NPTS];        // results: buckets then overflow

// ---------------------------------------------------------------------------
// Pack: [3,D,H,W] fp32 -> half4 voxels in E[i] and O[i-1]. Also zeros the
// bucket counters (ordering vs scatter is guaranteed by the kernel boundary).
// ---------------------------------------------------------------------------
__device__ __forceinline__ void pack_one(const float* __restrict__ s, int i, int nv,
                                         uint2* __restrict__ E, uint2* __restrict__ O)
{
    __half h0 = __float2half_rn(s[i]);
    __half h1 = __float2half_rn(s[i + nv]);
    __half h2 = __float2half_rn(s[i + 2 * nv]);
    __half2 lo = __halves2half2(h0, h1);
    __half2 hi = __halves2half2(h2, __ushort_as_half((unsigned short)0));
    uint2 u;
    u.x = *reinterpret_cast<unsigned int*>(&lo);
    u.y = *reinterpret_cast<unsigned int*>(&hi);
    E[i] = u;
    if (i > 0) O[i - 1] = u;
}

__global__ void __launch_bounds__(256) pack_kernel(
    const float* __restrict__ s0, const float* __restrict__ s1,
    const float* __restrict__ s2, const float* __restrict__ s3)
{
    int i = blockIdx.x * 256 + threadIdx.x;
    if (i < NB) g_cnt[i] = 0;                 // folded zero pass
    if (i == 0) g_novf = 0;
    if (i < NV0) { pack_one(s0, i, NV0, g_e0, g_o0); return; }
    i -= NV0;
    if (i < NV1) { pack_one(s1, i, NV1, g_e1, g_o1); return; }
    i -= NV1;
    if (i < NV2) { pack_one(s2, i, NV2, g_e2, g_o2); return; }
    i -= NV2;
    if (i < NV3) { pack_one(s3, i, NV3, g_e3, g_o3); }
}

// ---------------------------------------------------------------------------
// Scatter: single pass. pos = key*CAP + atomicAdd; overflow -> list.
// ---------------------------------------------------------------------------
__device__ __forceinline__ int coord_key(float gx, float gy, float gz)
{
    int bx = (int)(fminf(fmaxf((gx + 1.0f) * 0.5f, 0.0f), 0.999999f) * (float)SBX);
    int by = (int)(fminf(fmaxf((gy + 1.0f) * 0.5f, 0.0f), 0.999999f) * (float)SBY);
    int bz = (int)(fminf(fmaxf((gz + 1.0f) * 0.5f, 0.0f), 0.999999f) * (float)SBZ);
    bx = min(bx, SBX - 1); by = min(by, SBY - 1); bz = min(bz, SBZ - 1);
    return (bz * SBY + by) * SBX + bx;
}

__global__ void __launch_bounds__(256) scatter_kernel(const float* __restrict__ coords)
{
    __shared__ float sc[768];
    int t = threadIdx.x;
    int base = blockIdx.x * 256;
    const float4* c4 = reinterpret_cast<const float4*>(coords + (size_t)base * 3);
    if (t < 192) {
        float4 v = __ldg(c4 + t);
        sc[4 * t + 0] = v.x; sc[4 * t + 1] = v.y;
        sc[4 * t + 2] = v.z; sc[4 * t + 3] = v.w;
    }
    __syncthreads();

    float gx = sc[3 * t], gy = sc[3 * t + 1], gz = sc[3 * t + 2];
    int n = base + t;
    int key = coord_key(gx, gy, gz);
    int c = atomicAdd(&g_cnt[key], 1);
    if (c < CAP) {
        int pos = key * CAP + c;
        g_sorted[pos] = make_float4(gx, gy, gz, 0.0f);
        g_inv[n] = pos;
    } else {
        int j = atomicAdd(&g_novf, 1);
        g_ovf[j] = make_float4(gx, gy, gz, 0.0f);
        g_inv[n] = NSLOTS + j;
    }
}

// ---------------------------------------------------------------------------
// Trilinear sample. x-lerp in half2 on raw fp16 data; only the interpolated
// 3 channel values are converted to fp32 (3 cvt/pair vs 6). fp32 accumulate.
// ---------------------------------------------------------------------------
__device__ __forceinline__ void acc_pair(uint4 q, float w, __half2 fx2,
                                         float& ax, float& ay, float& az)
{
    __half2 a01 = *reinterpret_cast<__half2*>(&q.x);
    __half2 a2j = *reinterpret_cast<__half2*>(&q.y);   // (c2, 0)
    __half2 b01 = *reinterpret_cast<__half2*>(&q.z);
    __half2 b2j = *reinterpret_cast<__half2*>(&q.w);
    __half2 t01 = __hfma2(fx2, __hsub2(b01, a01), a01);
    __half2 t2  = __hfma2(fx2, __hsub2(b2j, a2j), a2j);
    float2 t01f = __half22float2(t01);
    float  t2f  = __low2float(t2);
    ax = fmaf(w, t01f.x, ax);
    ay = fmaf(w, t01f.y, ay);
    az = fmaf(w, t2f,    az);
}

template <int D, int H, int W>
__device__ __forceinline__ void sample_vol(
    const uint2* __restrict__ E, const uint2* __restrict__ O,
    float gx, float gy, float gz,
    float& ax, float& ay, float& az)
{
    const float hx = 0.5f * (float)(W - 1);
    const float hy = 0.5f * (float)(H - 1);
    const float hz = 0.5f * (float)(D - 1);
    float ix = fminf(fmaxf(fmaf(gx, hx, hx), 0.0f), (float)(W - 1));
    float iy = fminf(fmaxf(fmaf(gy, hy, hy), 0.0f), (float)(H - 1));
    float iz = fminf(fmaxf(fmaf(gz, hz, hz), 0.0f), (float)(D - 1));

    int x0 = min((int)ix, W - 2);
    int y0 = min((int)iy, H - 2);
    int z0 = min((int)iz, D - 2);
    float fx = ix - (float)x0;
    float fy = iy - (float)y0;
    float fz = iz - (float)z0;
    __half2 fx2 = __float2half2_rn(fx);

    int r00 = (z0 * H + y0) * W;
    int r01 = r00 + W;
    int r10 = r00 + H * W;
    int r11 = r10 + W;

    int odd = x0 & 1;
    const uint2* arr = odd ? O : E;
    int xo = x0 - odd;

    uint4 q00 = __ldg(reinterpret_cast<const uint4*>(arr + (r00 + xo)));
    uint4 q01 = __ldg(reinterpret_cast<const uint4*>(arr + (r01 + xo)));
    uint4 q10 = __ldg(reinterpret_cast<const uint4*>(arr + (r10 + xo)));
    uint4 q11 = __ldg(reinterpret_cast<const uint4*>(arr + (r11 + xo)));

    float ez = 1.0f - fz, ey = 1.0f - fy;
    acc_pair(q00, ez * ey, fx2, ax, ay, az);
    acc_pair(q01, ez * fy, fx2, ax, ay, az);
    acc_pair(q10, fz * ey, fx2, ax, ay, az);
    acc_pair(q11, fz * fy, fx2, ax, ay, az);
}

__device__ __forceinline__ float4 sample_all(float gx, float gy, float gz)
{
    float ax = 0.0f, ay = 0.0f, az = 0.0f;
    sample_vol<D0, H0, W0>(g_e0, g_o0, gx, gy, gz, ax, ay, az);
    sample_vol<D1, H1, W1>(g_e1, g_o1, gx, gy, gz, ax, ay, az);
    sample_vol<D2, H2, W2>(g_e2, g_o2, gx, gy, gz, ax, ay, az);
    sample_vol<D3, H3, W3>(g_e3, g_o3, gx, gy, gz, ax, ay, az);
    return make_float4(ax, ay, az, 0.0f);
}

// ---------------------------------------------------------------------------
// Bucket sample: one warp per bucket; lanes >= count inert.
// ---------------------------------------------------------------------------
__global__ void __launch_bounds__(256) sample_bucket_kernel()
{
    int warp = blockIdx.x * 8 + (threadIdx.x >> 5);
    int lane = threadIdx.x & 31;
    int cnt = min(g_cnt[warp], CAP);
    if (lane < cnt) {
        int pos = warp * CAP + lane;
        float4 c = g_sorted[pos];
        g_res[pos] = sample_all(c.x, c.y, c.z);
    }
}

// ---------------------------------------------------------------------------
// Overflow sample: grid-stride over the (tiny) overflow list, unsorted.
// ---------------------------------------------------------------------------
__global__ void __launch_bounds__(256) sample_ovf_kernel()
{
    int total = g_novf;
    for (int j = blockIdx.x * 256 + threadIdx.x; j < total; j += gridDim.x * 256) {
        float4 c = g_ovf[j];
        g_res[NSLOTS + j] = sample_all(c.x, c.y, c.z);
    }
}

// ---------------------------------------------------------------------------
// Unpermute: out[b][c][v] <- g_res[g_inv[n]]. 2 points/thread for gather MLP.
// ---------------------------------------------------------------------------
__global__ void __launch_bounds__(256) unpermute_kernel(float* __restrict__ out)
{
    int base = blockIdx.x * 512 + threadIdx.x;
    int m0 = base;
    int m1 = base + 256;
    int p0 = g_inv[m0];
    int p1 = g_inv[m1];
    float4 r0 = __ldg(&g_res[p0]);
    float4 r1 = __ldg(&g_res[p1]);

    int b0 = m0 / BVOL, v0 = m0 - b0 * BVOL;
    int b1 = m1 / BVOL, v1 = m1 - b1 * BVOL;
    float* o0 = out + (size_t)(b0 * 3) * BVOL + v0;
    float* o1 = out + (size_t)(b1 * 3) * BVOL + v1;
    o0[0] = r0.x;  o0[BVOL] = r0.y;  o0[2 * BVOL] = r0.z;
    o1[0] = r1.x;  o1[BVOL] = r1.y;  o1[2 * BVOL] = r1.z;
}

// ---------------------------------------------------------------------------
// Launch
// ---------------------------------------------------------------------------
extern "C" void kernel_launch(void* const* d_in, const int* in_sizes, int n_in,
                              void* d_out, int out_size)
{
    const float* coords = (const float*)d_in[0];
    const float* img0   = (const float*)d_in[1];
    const float* img1   = (const float*)d_in[2];
    const float* img2   = (const float*)d_in[3];
    const float* img3   = (const float*)d_in[4];
    float*       out    = (float*)d_out;

    pack_kernel<<<NV_TOTAL / 256, 256>>>(img0, img1, img2, img3);
    scatter_kernel<<<NPTS / 256, 256>>>(coords);
    sample_bucket_kernel<<<NB / 8, 256>>>();       // 1 warp per bucket
    sample_ovf_kernel<<<512, 256>>>();
    unpermute_kernel<<<NPTS / 512, 256>>>(out);
}